// round 11
// baseline (speedup 1.0000x reference)
#include <cuda_runtime.h>
#include <cstdint>

#define B_SZ 512
#define A_SZ 1024
#define XDIM 1024
#define NREL 500
#define MN (512 * 512)
#define SK 8
#define N2 768   // fused gemm2 output width: 256 (X2 cols 256..511) + 512 (M)

// scratch (device globals; no allocation allowed)
__device__ float g_X1p[SK * MN];          // gemm1 split-K partials
__device__ float g_X1[MN];                // relu(sum X1p + b1)
__device__ float g_X2Rp[SK * B_SZ * N2];  // fused gemm2 split-K partials
__device__ float g_Wt[512 * 256];         // W2[:256,:] transposed -> [512,256]
__device__ float g_M[512 * 512];          // rel_emb @ W2[:256,:]  (rows >=500 garbage)
__device__ float g_biasR[512];            // b2[:256] . rel_emb[j]

__device__ __forceinline__ float4 ld4(const float* p) { return *(const float4*)p; }

// ---------------------------------------------------------------------------
// SIMT SGEMM core (r6 single-buffer): 128x128 tile, BK=8, 256 threads,
// 8x8/thread. Warp tile 32(m) x 64(n); lanes 4(m) x 8(n). Conflict-free.
// A and B loads go through lambdas (fusion / guards at call site).
// ---------------------------------------------------------------------------
struct SgemmSmem {
    float As[8][128];
    float Bs[8][128];
};

template<typename ALOAD, typename BLOAD>
__device__ __forceinline__ void sgemm_core(
    SgemmSmem& sm, ALOAD aload, BLOAD bload,
    float* __restrict__ C, int ldc, int kbeg, int kchunk, int m0, int n0) {
    const int t = threadIdx.x;
    const int row = t >> 1;          // 0..127  (fill row)
    const int kq  = (t & 1) * 4;     // 0 or 4  (fill k sub-offset)
    const int w = t >> 5;
    const int lane = t & 31;
    const int tm = (w & 3) * 32 + (lane & 3) * 8;   // thread m offset
    const int tn = (w >> 2) * 64 + (lane >> 2) * 8; // thread n offset

    float acc[8][8];
    #pragma unroll
    for (int i = 0; i < 8; i++)
        #pragma unroll
        for (int j = 0; j < 8; j++) acc[i][j] = 0.f;

    // preload chunk 0
    float4 aReg = aload(m0 + row, kbeg + kq);
    float4 bReg = bload(n0 + row, kbeg + kq);

    const int nIter = kchunk >> 3;
    for (int it = 0; it < nIter; it++) {
        sm.As[kq + 0][row] = aReg.x; sm.As[kq + 1][row] = aReg.y;
        sm.As[kq + 2][row] = aReg.z; sm.As[kq + 3][row] = aReg.w;
        sm.Bs[kq + 0][row] = bReg.x; sm.Bs[kq + 1][row] = bReg.y;
        sm.Bs[kq + 2][row] = bReg.z; sm.Bs[kq + 3][row] = bReg.w;
        __syncthreads();

        if (it + 1 < nIter) {
            int k = kbeg + (it + 1) * 8 + kq;
            aReg = aload(m0 + row, k);
            bReg = bload(n0 + row, k);
        }

        #pragma unroll
        for (int kk = 0; kk < 8; kk++) {
            float a[8], b[8];
            *(float4*)&a[0] = *(const float4*)&sm.As[kk][tm];
            *(float4*)&a[4] = *(const float4*)&sm.As[kk][tm + 4];
            *(float4*)&b[0] = *(const float4*)&sm.Bs[kk][tn];
            *(float4*)&b[4] = *(const float4*)&sm.Bs[kk][tn + 4];
            #pragma unroll
            for (int i = 0; i < 8; i++)
                #pragma unroll
                for (int j = 0; j < 8; j++)
                    acc[i][j] = fmaf(a[i], b[j], acc[i][j]);
        }
        __syncthreads();
    }

    #pragma unroll
    for (int i = 0; i < 8; i++) {
        int m = m0 + tm + i;
        *(float4*)&C[(size_t)m * ldc + n0 + tn] =
            make_float4(acc[i][0], acc[i][1], acc[i][2], acc[i][3]);
        *(float4*)&C[(size_t)m * ldc + n0 + tn + 4] =
            make_float4(acc[i][4], acc[i][5], acc[i][6], acc[i][7]);
    }
}

// ---------------------------------------------------------------------------
// Prep: Wt[k][c] = W2[c][k] (c<256, k<512)  +  biasR[j] = b2[:256].rel[j]
// grid 514, block 256. Blocks 0..511 transpose; 512..513 compute biasR.
// ---------------------------------------------------------------------------
__global__ void __launch_bounds__(256) prep_kernel(
    const float* __restrict__ W2, const float* __restrict__ b2,
    const float* __restrict__ rel) {
    int bx = blockIdx.x;
    if (bx < 512) {
        int idx = bx * 256 + threadIdx.x;   // 131072 elements
        int k = idx >> 8, c = idx & 255;
        g_Wt[idx] = W2[(size_t)c * 512 + k];
    } else {
        int j = (bx - 512) * 256 + threadIdx.x;
        float s = 0.f;
        if (j < NREL) {
            const float* rj = rel + (size_t)j * 256;
            for (int c = 0; c < 256; c++) s += b2[c] * rj[c];
        }
        g_biasR[j] = s;
    }
}

// ---------------------------------------------------------------------------
// M = rel_emb @ Wt^T   (M[j,k] = sum_c rel[j,c] W2[c,k]).  grid (4,4), K=256.
// Rows >= 500 read rel row 0 (results garbage but finite; never consumed).
// ---------------------------------------------------------------------------
__global__ void __launch_bounds__(256) gemm_M(const float* __restrict__ rel) {
    __shared__ SgemmSmem sm;
    auto aload = [&](int m, int k) -> float4 {
        int mm = m < NREL ? m : 0;
        return ld4(rel + (size_t)mm * 256 + k);
    };
    auto bload = [&](int n, int k) -> float4 {
        return ld4(g_Wt + (size_t)n * 256 + k);
    };
    sgemm_core(sm, aload, bload, g_M, 512, 0, 256,
               blockIdx.y * 128, blockIdx.x * 128);
}

// ---------------------------------------------------------------------------
// GEMM1 (concat fused): X1p[z] = seg(z) @ W1^T chunk. grid (4,4,8), chunk 128.
// ---------------------------------------------------------------------------
__global__ void __launch_bounds__(256) gemm1_fused(
    const float* __restrict__ e_t, const float* __restrict__ Hs,
    const float* __restrict__ r_q, const float* __restrict__ W1) {
    __shared__ SgemmSmem sm;
    int z = blockIdx.z;
    const float* A; int lda, colb;
    if (z < 2)      { A = e_t; lda = 256; colb = z * 128; }
    else if (z < 6) { A = Hs;  lda = 512; colb = (z - 2) * 128; }
    else            { A = r_q; lda = 256; colb = (z - 6) * 128; }
    int kbeg = z * 128;
    auto aload = [&](int m, int k) -> float4 {
        return ld4(A + (size_t)m * lda + colb + (k - kbeg));
    };
    auto bload = [&](int n, int k) -> float4 {
        return ld4(W1 + (size_t)n * XDIM + k);
    };
    sgemm_core(sm, aload, bload, g_X1p + (size_t)z * MN, 512,
               kbeg, 128, blockIdx.y * 128, blockIdx.x * 128);
}

// ---------------------------------------------------------------------------
// X1 = relu(sum_p X1p[p] + b1)
// ---------------------------------------------------------------------------
__global__ void __launch_bounds__(256) reduce_x1(const float* __restrict__ b1) {
    int i = blockIdx.x * 256 + threadIdx.x;
    float s = 0.f;
    #pragma unroll
    for (int p = 0; p < SK; p++) s += g_X1p[(size_t)p * MN + i];
    s += b1[i & 511];
    g_X1[i] = fmaxf(s, 0.f);
}

// ---------------------------------------------------------------------------
// Fused GEMM2: X2Rp[z] = X1 @ [W2[256:,:] | M]^T chunk.  grid (6,4,8), N=768.
// cols 0..255  -> X2[:, 256:512];  cols 256..767 -> relS (valid 256..755).
// ---------------------------------------------------------------------------
__global__ void __launch_bounds__(256) gemm2_fused(const float* __restrict__ W2) {
    __shared__ SgemmSmem sm;
    auto aload = [&](int m, int k) -> float4 {
        return ld4(g_X1 + (size_t)m * 512 + k);
    };
    auto bload = [&](int n, int k) -> float4 {
        return (n < 256) ? ld4(W2 + (size_t)(256 + n) * 512 + k)
                         : ld4(g_M + (size_t)(n - 256) * 512 + k);
    };
    int z = blockIdx.z;
    sgemm_core(sm, aload, bload, g_X2Rp + (size_t)z * (B_SZ * N2), N2,
               z * 64, 64, blockIdx.y * 128, blockIdx.x * 128);
}

// ---------------------------------------------------------------------------
// Threefry-2x32 (20 rounds). JAX partitionable bits = o0 ^ o1, counter (0, i).
// ---------------------------------------------------------------------------
__device__ __forceinline__ uint32_t jax_bits(uint32_t i) {
    uint32_t k0 = 0u, k1 = 42u;
    uint32_t k2 = k0 ^ k1 ^ 0x1BD11BDAu;
    uint32_t x0 = k0, x1 = i + k1;
#define TF_R(r) { x0 += x1; x1 = (x1 << (r)) | (x1 >> (32 - (r))); x1 ^= x0; }
    TF_R(13) TF_R(15) TF_R(26) TF_R(6)   x0 += k1; x1 += k2 + 1u;
    TF_R(17) TF_R(29) TF_R(16) TF_R(24)  x0 += k2; x1 += k0 + 2u;
    TF_R(13) TF_R(15) TF_R(26) TF_R(6)   x0 += k0; x1 += k1 + 3u;
    TF_R(17) TF_R(29) TF_R(16) TF_R(24)  x0 += k1; x1 += k2 + 4u;
    TF_R(13) TF_R(15) TF_R(26) TF_R(6)   x0 += k2; x1 += k0 + 5u;
#undef TF_R
    return x0 ^ x1;
}

__device__ __forceinline__ float dot8(float4 v0, float4 v1, const float* x) {
    return v0.x * x[0] + v0.y * x[1] + v0.z * x[2] + v0.w * x[3]
         + v1.x * x[4] + v1.y * x[5] + v1.z * x[6] + v1.w * x[7];
}

// ---------------------------------------------------------------------------
// Gather + masked softmax + entropy + gumbel argmax. 1 block/row, 512 threads.
// Pre-reduces the fused partials: sX2 from cols 0..255, sRel from 256..767.
// ---------------------------------------------------------------------------
__global__ void __launch_bounds__(512) score_softmax_sample(
    const int* __restrict__ r_space,
    const int* __restrict__ e_space,
    const float* __restrict__ mask,
    const float* __restrict__ ent_emb,
    const float* __restrict__ W2_b,
    float* __restrict__ out) {
    int b = blockIdx.x;
    int tid = threadIdx.x;
    int lane = tid & 31;
    int w = tid >> 5;           // 0..15

    __shared__ float sX2[256];
    __shared__ float sRel[512];
    __shared__ float sSc[1024];
    __shared__ float sMax[16];
    __shared__ float sSum[16];
    __shared__ float sV[16];
    __shared__ float sE[16];
    __shared__ int   sI[16];

    // pre-reduce fused partials for this row
    {
        float v = g_biasR[tid];
        #pragma unroll
        for (int p = 0; p < SK; p++)
            v += g_X2Rp[(size_t)p * (B_SZ * N2) + (size_t)b * N2 + 256 + tid];
        sRel[tid] = v;
    }
    if (tid < 256) {
        float v = W2_b[256 + tid];
        #pragma unroll
        for (int p = 0; p < SK; p++)
            v += g_X2Rp[(size_t)p * (B_SZ * N2) + (size_t)b * N2 + tid];
        sX2[tid] = v;
    }
    __syncthreads();

    float x[8];
    #pragma unroll
    for (int j = 0; j < 8; j++) x[j] = sX2[lane * 8 + j];

    const int base = b * A_SZ;

    // ---- scores (4 actions in flight per warp) ----
    for (int it = 0; it < 64; it += 4) {
        int a0 = w * 64 + it;
        float s[4];
        #pragma unroll
        for (int q = 0; q < 4; q++) {
            int e = e_space[base + a0 + q];
            const float4* ep = (const float4*)(ent_emb + (size_t)e * 256 + lane * 8);
            float4 v0 = ep[0], v1 = ep[1];
            s[q] = dot8(v0, v1, x);
        }
        #pragma unroll
        for (int o = 16; o; o >>= 1) {
            #pragma unroll
            for (int q = 0; q < 4; q++)
                s[q] += __shfl_xor_sync(0xFFFFFFFFu, s[q], o);
        }
        if (lane == 0) {
            #pragma unroll
            for (int q = 0; q < 4; q++) {
                int a = a0 + q;
                int r = r_space[base + a];
                sSc[a] = s[q] + sRel[r] - (1.0f - mask[base + a]) * 1e9f;
            }
        }
    }
    __syncthreads();

    // ---- max ----
    float mx = -__int_as_float(0x7F800000);
    for (int j = tid; j < 1024; j += 512) mx = fmaxf(mx, sSc[j]);
    #pragma unroll
    for (int o = 16; o; o >>= 1) mx = fmaxf(mx, __shfl_xor_sync(0xFFFFFFFFu, mx, o));
    if (lane == 0) sMax[w] = mx;
    __syncthreads();
    mx = sMax[0];
    #pragma unroll
    for (int i = 1; i < 16; i++) mx = fmaxf(mx, sMax[i]);

    // ---- exp & sum ----
    float sum = 0.f;
    for (int j = tid; j < 1024; j += 512) {
        float e = expf(sSc[j] - mx);
        sSc[j] = e;
        sum += e;
    }
    #pragma unroll
    for (int o = 16; o; o >>= 1) sum += __shfl_xor_sync(0xFFFFFFFFu, sum, o);
    if (lane == 0) sSum[w] = sum;
    __syncthreads();
    float total = 0.f;
    #pragma unroll
    for (int i = 0; i < 16; i++) total += sSum[i];

    // ---- p, entropy, gumbel argmax ----
    float ent = 0.f;
    float bestV = -__int_as_float(0x7F800000);
    int bestI = 0x7FFFFFFF;
    for (int j = tid; j < 1024; j += 512) {
        float p = sSc[j] / total;
        sSc[j] = p;
        out[1536 + base + j] = p;                 // action_dist
        float lp = logf(p + 1e-30f);
        ent += p * lp;
        uint32_t bits = jax_bits((uint32_t)(base + j));
        float f = __uint_as_float((bits >> 9) | 0x3F800000u) - 1.0f;
        float u = fmaxf(f, 1.17549435e-38f);
        float g = -logf(-logf(u));
        float v = lp + g;
        if (v > bestV || (v == bestV && j < bestI)) { bestV = v; bestI = j; }
    }
    #pragma unroll
    for (int o = 16; o; o >>= 1) {
        float ov = __shfl_xor_sync(0xFFFFFFFFu, bestV, o);
        int   oi = __shfl_xor_sync(0xFFFFFFFFu, bestI, o);
        float oe = __shfl_xor_sync(0xFFFFFFFFu, ent, o);
        ent += oe;
        if (ov > bestV || (ov == bestV && oi < bestI)) { bestV = ov; bestI = oi; }
    }
    if (lane == 0) { sV[w] = bestV; sI[w] = bestI; sE[w] = ent; }
    __syncthreads();

    if (tid == 0) {
        float bv = sV[0]; int bi = sI[0]; float te = sE[0];
        #pragma unroll
        for (int i = 1; i < 16; i++) {
            te += sE[i];
            if (sV[i] > bv || (sV[i] == bv && sI[i] < bi)) { bv = sV[i]; bi = sI[i]; }
        }
        out[b]        = sSc[bi];                          // action_prob
        out[512 + b]  = (float)r_space[base + bi];        // next_r
        out[1024 + b] = (float)e_space[base + bi];        // next_e
        out[525824 + b] = -te;                            // entropy
    }
}

// ---------------------------------------------------------------------------
extern "C" void kernel_launch(void* const* d_in, const int* in_sizes, int n_in,
                              void* d_out, int out_size) {
    const float* e_t     = (const float*)d_in[0];
    const float* Hs      = (const float*)d_in[1];
    const float* r_q     = (const float*)d_in[2];
    const int*   r_space = (const int*)d_in[3];
    const int*   e_space = (const int*)d_in[4];
    const float* mask    = (const float*)d_in[5];
    const float* W1_w    = (const float*)d_in[6];
    const float* W1_b    = (const float*)d_in[7];
    const float* W2_w    = (const float*)d_in[8];
    const float* W2_b    = (const float*)d_in[9];
    const float* rel_emb = (const float*)d_in[10];
    const float* ent_emb = (const float*)d_in[11];
    float* out = (float*)d_out;

    // Wt = W2[:256,:]^T ; biasR = rel_emb @ b2[:256]
    prep_kernel<<<514, 256>>>(W2_w, W2_b, rel_emb);
    // M = rel_emb @ Wt^T
    gemm_M<<<dim3(4, 4), 256>>>(rel_emb);
    // X1p[z] = concat @ W1^T  (K=1024, SK=8, chunk 128)
    gemm1_fused<<<dim3(4, 4, SK), 256>>>(e_t, Hs, r_q, W1_w);
    // X1 = relu(sum + b1)
    reduce_x1<<<MN / 256, 256>>>(W1_b);
    // X2Rp[z] = X1 @ [W2[256:,:] | M]^T  (K=512, SK=8, chunk 64)
    gemm2_fused<<<dim3(6, 4, SK), 256>>>(W2_w);
    // gather + softmax + entropy + sample
    score_softmax_sample<<<B_SZ, 512>>>(r_space, e_space, mask, ent_emb, W2_b, out);
}

// round 12
// speedup vs baseline: 1.6630x; 1.6630x over previous
#include <cuda_runtime.h>
#include <cstdint>

#define B_SZ 512
#define A_SZ 1024
#define XDIM 1024
#define NREL 500
#define MN (512 * 512)
#define SK 8

// scratch (device globals; no allocation allowed)
__device__ float g_X1p[SK * MN];   // gemm1 split-K partials
__device__ float g_X1[MN];         // relu(sum X1p + b1)
__device__ float g_X2p[SK * MN];   // gemm2 split-K partials
__device__ float g_relSp[SK * MN]; // relS split-K partials

__device__ __forceinline__ float4 ld4(const float* p) { return *(const float4*)p; }

// ---------------------------------------------------------------------------
// SIMT SGEMM core: 128(m) x 64(n) tile, BK=8, 256 threads (8 warps),
// 8m x 4n per thread -> 32 accs, ~60 regs -> 2 blocks/SM (4 warps/SMSP).
// Warps 4(m) x 2(n) (warp tile 32x32); lanes 4(m) x 8(n).
// A frag: 4 distinct 16B lines x 8-bcast; B frag: 8 lines x 4-bcast. No conflicts.
// ---------------------------------------------------------------------------
struct SgemmSmem {
    float As[8][128];
    float Bs[8][64];
};

template<typename ALOAD>
__device__ __forceinline__ void sgemm_core(
    SgemmSmem& sm, ALOAD aload,
    const float* __restrict__ Bm, int ldb, int NB,
    float* __restrict__ C, int kbeg, int kchunk, int m0, int n0) {
    const int t = threadIdx.x;
    const int row = t >> 1;          // 0..127 (A fill row)
    const int kq  = (t & 1) * 4;     // 0 or 4
    const int w = t >> 5;
    const int lane = t & 31;
    const int tm = (w & 3) * 32 + (lane & 3) * 8;    // 8 m-rows
    const int tn = (w >> 2) * 32 + (lane >> 2) * 4;  // 4 n-cols

    float acc[8][4];
    #pragma unroll
    for (int i = 0; i < 8; i++)
        #pragma unroll
        for (int j = 0; j < 4; j++) acc[i][j] = 0.f;

    // preload chunk 0 (B loaded by threads 0..127 only: 64 rows x 2 k-quads)
    float4 aReg = aload(m0 + row, kbeg + kq);
    float4 bReg = make_float4(0.f, 0.f, 0.f, 0.f);
    if (t < 128 && n0 + row < NB)
        bReg = ld4(Bm + (size_t)(n0 + row) * ldb + kbeg + kq);

    const int nIter = kchunk >> 3;
    for (int it = 0; it < nIter; it++) {
        sm.As[kq + 0][row] = aReg.x; sm.As[kq + 1][row] = aReg.y;
        sm.As[kq + 2][row] = aReg.z; sm.As[kq + 3][row] = aReg.w;
        if (t < 128) {
            sm.Bs[kq + 0][row] = bReg.x; sm.Bs[kq + 1][row] = bReg.y;
            sm.Bs[kq + 2][row] = bReg.z; sm.Bs[kq + 3][row] = bReg.w;
        }
        __syncthreads();

        if (it + 1 < nIter) {
            int k = kbeg + (it + 1) * 8 + kq;
            aReg = aload(m0 + row, k);
            if (t < 128 && n0 + row < NB)
                bReg = ld4(Bm + (size_t)(n0 + row) * ldb + k);
        }

        #pragma unroll
        for (int kk = 0; kk < 8; kk++) {
            float a[8], b[4];
            *(float4*)&a[0] = *(const float4*)&sm.As[kk][tm];
            *(float4*)&a[4] = *(const float4*)&sm.As[kk][tm + 4];
            *(float4*)&b[0] = *(const float4*)&sm.Bs[kk][tn];
            #pragma unroll
            for (int i = 0; i < 8; i++)
                #pragma unroll
                for (int j = 0; j < 4; j++)
                    acc[i][j] = fmaf(a[i], b[j], acc[i][j]);
        }
        __syncthreads();
    }

    #pragma unroll
    for (int i = 0; i < 8; i++) {
        int m = m0 + tm + i;
        *(float4*)&C[(size_t)m * 512 + n0 + tn] =
            make_float4(acc[i][0], acc[i][1], acc[i][2], acc[i][3]);
    }
}

// ---------------------------------------------------------------------------
// GEMM1 (concat fused): X1p[z] = seg(z) @ W1^T chunk. grid (8, 4, 8), chunk 128.
// k range [z*128, z*128+128): z 0-1 e_t, 2-5 H, 6-7 r_q.
// ---------------------------------------------------------------------------
__global__ void __launch_bounds__(256) gemm1_fused(
    const float* __restrict__ e_t, const float* __restrict__ Hs,
    const float* __restrict__ r_q, const float* __restrict__ W1) {
    __shared__ SgemmSmem sm;
    int z = blockIdx.z;
    const float* A; int lda, colb;
    if (z < 2)      { A = e_t; lda = 256; colb = z * 128; }
    else if (z < 6) { A = Hs;  lda = 512; colb = (z - 2) * 128; }
    else            { A = r_q; lda = 256; colb = (z - 6) * 128; }
    int kbeg = z * 128;
    auto aload = [&](int m, int k) -> float4 {
        return ld4(A + (size_t)m * lda + colb + (k - kbeg));
    };
    sgemm_core(sm, aload, W1, XDIM, 512, g_X1p + (size_t)z * MN,
               kbeg, 128, blockIdx.y * 128, blockIdx.x * 64);
}

// ---------------------------------------------------------------------------
// X1 = relu(sum_p X1p[p] + b1)
// ---------------------------------------------------------------------------
__global__ void __launch_bounds__(256) reduce_x1(const float* __restrict__ b1) {
    int i = blockIdx.x * 256 + threadIdx.x;
    float s = 0.f;
    #pragma unroll
    for (int p = 0; p < SK; p++) s += g_X1p[(size_t)p * MN + i];
    s += b1[i & 511];
    g_X1[i] = fmaxf(s, 0.f);
}

// ---------------------------------------------------------------------------
// Generic split-K GEMM (A = sum of APART partials + optional bias).
// ---------------------------------------------------------------------------
template<int APART, bool ABIAS>
__global__ void __launch_bounds__(256) gemm_sk(
    const float* __restrict__ A, const float* __restrict__ Abias, int lda,
    const float* __restrict__ Bm, int ldb, int NB,
    float* __restrict__ Cp, int kchunk) {
    __shared__ SgemmSmem sm;
    auto aload = [&](int m, int k) -> float4 {
        float4 v = ld4(A + (size_t)m * lda + k);
        #pragma unroll
        for (int p = 1; p < APART; p++) {
            float4 u = ld4(A + (size_t)p * MN + (size_t)m * lda + k);
            v.x += u.x; v.y += u.y; v.z += u.z; v.w += u.w;
        }
        if (ABIAS) {
            float4 bv = ld4(Abias + k);
            v.x += bv.x; v.y += bv.y; v.z += bv.z; v.w += bv.w;
        }
        return v;
    };
    sgemm_core(sm, aload, Bm, ldb, NB, Cp + (size_t)blockIdx.z * MN,
               blockIdx.z * kchunk, kchunk, blockIdx.y * 128, blockIdx.x * 64);
}

// ---------------------------------------------------------------------------
// Threefry-2x32 (20 rounds). JAX partitionable bits = o0 ^ o1, counter (0, i).
// ---------------------------------------------------------------------------
__device__ __forceinline__ uint32_t jax_bits(uint32_t i) {
    uint32_t k0 = 0u, k1 = 42u;
    uint32_t k2 = k0 ^ k1 ^ 0x1BD11BDAu;
    uint32_t x0 = k0, x1 = i + k1;
#define TF_R(r) { x0 += x1; x1 = (x1 << (r)) | (x1 >> (32 - (r))); x1 ^= x0; }
    TF_R(13) TF_R(15) TF_R(26) TF_R(6)   x0 += k1; x1 += k2 + 1u;
    TF_R(17) TF_R(29) TF_R(16) TF_R(24)  x0 += k2; x1 += k0 + 2u;
    TF_R(13) TF_R(15) TF_R(26) TF_R(6)   x0 += k0; x1 += k1 + 3u;
    TF_R(17) TF_R(29) TF_R(16) TF_R(24)  x0 += k1; x1 += k2 + 4u;
    TF_R(13) TF_R(15) TF_R(26) TF_R(6)   x0 += k2; x1 += k0 + 5u;
#undef TF_R
    return x0 ^ x1;
}

__device__ __forceinline__ float dot8(float4 v0, float4 v1, const float* x) {
    return v0.x * x[0] + v0.y * x[1] + v0.z * x[2] + v0.w * x[3]
         + v1.x * x[4] + v1.y * x[5] + v1.z * x[6] + v1.w * x[7];
}

// ---------------------------------------------------------------------------
// Gather + masked softmax + entropy + gumbel argmax. 1 block/row, 512 threads.
// relS partials pre-reduced into smem once per row. (identical to r6)
// ---------------------------------------------------------------------------
__global__ void __launch_bounds__(512) score_softmax_sample(
    const int* __restrict__ r_space,
    const int* __restrict__ e_space,
    const float* __restrict__ mask,
    const float* __restrict__ ent_emb,
    const float* __restrict__ W2_b,
    float* __restrict__ out) {
    int b = blockIdx.x;
    int tid = threadIdx.x;
    int lane = tid & 31;
    int w = tid >> 5;           // 0..15

    __shared__ float sX2[256];
    __shared__ float sRel[512];
    __shared__ float sSc[1024];
    __shared__ float sMax[16];
    __shared__ float sSum[16];
    __shared__ float sV[16];
    __shared__ float sE[16];
    __shared__ int   sI[16];

    // pre-reduce relS partials for this row
    {
        float v = 0.f;
        #pragma unroll
        for (int p = 0; p < SK; p++) v += g_relSp[(size_t)p * MN + b * 512 + tid];
        sRel[tid] = v;
    }
    if (tid < 256) {
        float v = W2_b[256 + tid];
        #pragma unroll
        for (int p = 0; p < SK; p++) v += g_X2p[(size_t)p * MN + b * 512 + 256 + tid];
        sX2[tid] = v;
    }
    __syncthreads();

    float x[8];
    #pragma unroll
    for (int j = 0; j < 8; j++) x[j] = sX2[lane * 8 + j];

    const int base = b * A_SZ;

    // ---- scores (4 actions in flight per warp) ----
    for (int it = 0; it < 64; it += 4) {
        int a0 = w * 64 + it;
        float s[4];
        #pragma unroll
        for (int q = 0; q < 4; q++) {
            int e = e_space[base + a0 + q];
            const float4* ep = (const float4*)(ent_emb + (size_t)e * 256 + lane * 8);
            float4 v0 = ep[0], v1 = ep[1];
            s[q] = dot8(v0, v1, x);
        }
        #pragma unroll
        for (int o = 16; o; o >>= 1) {
            #pragma unroll
            for (int q = 0; q < 4; q++)
                s[q] += __shfl_xor_sync(0xFFFFFFFFu, s[q], o);
        }
        if (lane == 0) {
            #pragma unroll
            for (int q = 0; q < 4; q++) {
                int a = a0 + q;
                int r = r_space[base + a];
                sSc[a] = s[q] + sRel[r] - (1.0f - mask[base + a]) * 1e9f;
            }
        }
    }
    __syncthreads();

    // ---- max ----
    float mx = -__int_as_float(0x7F800000);
    for (int j = tid; j < 1024; j += 512) mx = fmaxf(mx, sSc[j]);
    #pragma unroll
    for (int o = 16; o; o >>= 1) mx = fmaxf(mx, __shfl_xor_sync(0xFFFFFFFFu, mx, o));
    if (lane == 0) sMax[w] = mx;
    __syncthreads();
    mx = sMax[0];
    #pragma unroll
    for (int i = 1; i < 16; i++) mx = fmaxf(mx, sMax[i]);

    // ---- exp & sum ----
    float sum = 0.f;
    for (int j = tid; j < 1024; j += 512) {
        float e = expf(sSc[j] - mx);
        sSc[j] = e;
        sum += e;
    }
    #pragma unroll
    for (int o = 16; o; o >>= 1) sum += __shfl_xor_sync(0xFFFFFFFFu, sum, o);
    if (lane == 0) sSum[w] = sum;
    __syncthreads();
    float total = 0.f;
    #pragma unroll
    for (int i = 0; i < 16; i++) total += sSum[i];

    // ---- p, entropy, gumbel argmax ----
    float ent = 0.f;
    float bestV = -__int_as_float(0x7F800000);
    int bestI = 0x7FFFFFFF;
    for (int j = tid; j < 1024; j += 512) {
        float p = sSc[j] / total;
        sSc[j] = p;
        out[1536 + base + j] = p;                 // action_dist
        float lp = logf(p + 1e-30f);
        ent += p * lp;
        uint32_t bits = jax_bits((uint32_t)(base + j));
        float f = __uint_as_float((bits >> 9) | 0x3F800000u) - 1.0f;
        float u = fmaxf(f, 1.17549435e-38f);
        float g = -logf(-logf(u));
        float v = lp + g;
        if (v > bestV || (v == bestV && j < bestI)) { bestV = v; bestI = j; }
    }
    #pragma unroll
    for (int o = 16; o; o >>= 1) {
        float ov = __shfl_xor_sync(0xFFFFFFFFu, bestV, o);
        int   oi = __shfl_xor_sync(0xFFFFFFFFu, bestI, o);
        float oe = __shfl_xor_sync(0xFFFFFFFFu, ent, o);
        ent += oe;
        if (ov > bestV || (ov == bestV && oi < bestI)) { bestV = ov; bestI = oi; }
    }
    if (lane == 0) { sV[w] = bestV; sI[w] = bestI; sE[w] = ent; }
    __syncthreads();

    if (tid == 0) {
        float bv = sV[0]; int bi = sI[0]; float te = sE[0];
        #pragma unroll
        for (int i = 1; i < 16; i++) {
            te += sE[i];
            if (sV[i] > bv || (sV[i] == bv && sI[i] < bi)) { bv = sV[i]; bi = sI[i]; }
        }
        out[b]        = sSc[bi];                          // action_prob
        out[512 + b]  = (float)r_space[base + bi];        // next_r
        out[1024 + b] = (float)e_space[base + bi];        // next_e
        out[525824 + b] = -te;                            // entropy
    }
}

// ---------------------------------------------------------------------------
extern "C" void kernel_launch(void* const* d_in, const int* in_sizes, int n_in,
                              void* d_out, int out_size) {
    const float* e_t     = (const float*)d_in[0];
    const float* Hs      = (const float*)d_in[1];
    const float* r_q     = (const float*)d_in[2];
    const int*   r_space = (const int*)d_in[3];
    const int*   e_space = (const int*)d_in[4];
    const float* mask    = (const float*)d_in[5];
    const float* W1_w    = (const float*)d_in[6];
    const float* W1_b    = (const float*)d_in[7];
    const float* W2_w    = (const float*)d_in[8];
    const float* W2_b    = (const float*)d_in[9];
    const float* rel_emb = (const float*)d_in[10];
    const float* ent_emb = (const float*)d_in[11];
    float* out = (float*)d_out;

    float *X1, *X2p, *relSp;
    cudaGetSymbolAddress((void**)&X1,    g_X1);
    cudaGetSymbolAddress((void**)&X2p,   g_X2p);
    cudaGetSymbolAddress((void**)&relSp, g_relSp);

    // X1p[z] = concat @ W1^T  (K=1024, SK=8, chunk 128)
    gemm1_fused<<<dim3(8, 4, SK), 256>>>(e_t, Hs, r_q, W1_w);
    // X1 = relu(sum + b1)
    reduce_x1<<<MN / 256, 256>>>(W1_b);
    // X2p[z] = X1 @ W2^T  (K=512, SK=8, chunk 64)
    gemm_sk<1, false><<<dim3(8, 4, SK), 256>>>(X1, nullptr, 512, W2_w, 512, 512, X2p, 64);
    // relSp[z] = (sum X2p + b2)[:, :256] @ rel_emb^T  (K=256, SK=8, chunk 32)
    gemm_sk<8, true><<<dim3(8, 4, SK), 256>>>(X2p, W2_b, 512, rel_emb, 256, NREL, relSp, 32);
    // gather + softmax + entropy + sample
    score_softmax_sample<<<B_SZ, 512>>>(r_space, e_space, mask, ent_emb, W2_b, out);
}